// round 4
// baseline (speedup 1.0000x reference)
#include <cuda_runtime.h>

#define NPIX 65536      // B*H*W = 64*32*32
#define DDIM 256
#define KCODES 512
#define MT 32           // pixels per CTA
#define KT 128          // codes per K-chunk
#define DCHUNK 8        // d per streamed chunk
#define ZS_STRIDE 260   // 256 + 4 (floats)
#define ES_STRIDE 12    // 8 + 4 pad: 8 lanes hit banks {0,12,24,4,16,28,8,20} — conflict-free
#define THREADS 128
#define NDC (DDIM / DCHUNK)   // 32 d-chunks
#define NKC (KCODES / KT)     // 4 k-chunks
#define TCH (NKC * NDC)       // 128 total chunks

__device__ float g_esq[KCODES];

__global__ void esq_kernel(const float* __restrict__ cb) {
    int k = blockIdx.x * blockDim.x + threadIdx.x;
    if (k >= KCODES) return;
    const float4* row = (const float4*)(cb + k * DDIM);
    float sx = 0.f, sy = 0.f, sz = 0.f, sw = 0.f;
#pragma unroll
    for (int i = 0; i < DDIM / 4; i++) {
        float4 v = row[i];
        sx = __fadd_rn(sx, __fmul_rn(v.x, v.x));
        sy = __fadd_rn(sy, __fmul_rn(v.y, v.y));
        sz = __fadd_rn(sz, __fmul_rn(v.z, v.z));
        sw = __fadd_rn(sw, __fmul_rn(v.w, v.w));
    }
    g_esq[k] = __fadd_rn(__fadd_rn(sx, sy), __fadd_rn(sz, sw));
}

__global__ __launch_bounds__(THREADS)
void vq_argmin_kernel(const float* __restrict__ z,
                      const float* __restrict__ cb,
                      float* __restrict__ out) {
    // Static shared: 45,696 bytes (< 48 KB, no opt-in needed)
    __shared__ float z_s[MT * ZS_STRIDE];
    __shared__ float e_s[2 * KT * ES_STRIDE];
    __shared__ float zsq_s[MT];

    const int tid   = threadIdx.x;
    const int c_id  = tid & 15;     // 16 code lanes
    const int px_id = tid >> 4;     // 8 pixel groups of 4
    const int pix_base = blockIdx.x * MT;

    // ---- transpose z tile: gmem [b, d, hw] -> z_s[p][d] ----
    {
        const int b   = pix_base >> 10;
        const int hw0 = pix_base & 1023;
        const float* zbase = z + (size_t)b * (DDIM * 1024) + hw0;
#pragma unroll
        for (int it = 0; it < 16; it++) {
            int linear = tid + THREADS * it;      // 0..2047 float4s
            int d  = linear >> 3;                 // 0..255
            int p4 = (linear & 7) << 2;           // 0..28
            float4 v = *(const float4*)(zbase + (size_t)d * 1024 + p4);
            z_s[(p4 + 0) * ZS_STRIDE + d] = v.x;
            z_s[(p4 + 1) * ZS_STRIDE + d] = v.y;
            z_s[(p4 + 2) * ZS_STRIDE + d] = v.z;
            z_s[(p4 + 3) * ZS_STRIDE + d] = v.w;
        }
    }
    __syncthreads();

    // ---- per-pixel |z|^2: square rounded separately, 4-lane pairwise sum ----
    if (tid < MT) {
        const float4* zr = (const float4*)(z_s + tid * ZS_STRIDE);
        float sx = 0.f, sy = 0.f, sz = 0.f, sw = 0.f;
#pragma unroll
        for (int i = 0; i < DDIM / 4; i++) {
            float4 v = zr[i];
            sx = __fadd_rn(sx, __fmul_rn(v.x, v.x));
            sy = __fadd_rn(sy, __fmul_rn(v.y, v.y));
            sz = __fadd_rn(sz, __fmul_rn(v.z, v.z));
            sw = __fadd_rn(sw, __fmul_rn(v.w, v.w));
        }
        zsq_s[tid] = __fadd_rn(__fadd_rn(sx, sy), __fadd_rn(sz, sw));
    }

    // ---- prefetch chunk 0 (kc=0, dc=0) into buffer 0 ----
    float4 pf0, pf1;
    {
        int i0 = tid, i1 = tid + THREADS;         // 0..255 float4 slots
        pf0 = *(const float4*)(cb + (size_t)(i0 >> 1) * DDIM + (i0 & 1) * 4);
        pf1 = *(const float4*)(cb + (size_t)(i1 >> 1) * DDIM + (i1 & 1) * 4);
        *(float4*)(e_s + (i0 >> 1) * ES_STRIDE + (i0 & 1) * 4) = pf0;
        *(float4*)(e_s + (i1 >> 1) * ES_STRIDE + (i1 & 1) * 4) = pf1;
    }
    __syncthreads();

    float best[4];
    int   bidx[4];
    float acc[4][8];
#pragma unroll
    for (int i = 0; i < 4; i++) {
        best[i] = 3.4e38f; bidx[i] = 0;
#pragma unroll
        for (int j = 0; j < 8; j++) acc[i][j] = 0.0f;
    }

    for (int t = 0; t < TCH; t++) {
        const int cur = t & 1;
        const int dc  = t & (NDC - 1);

        // issue prefetch of chunk t+1 (gmem latency overlaps compute)
        if (t + 1 < TCH) {
            const int nk = (t + 1) >> 5;          // next k-chunk
            const int nd = (t + 1) & (NDC - 1);   // next d-chunk
            int i0 = tid, i1 = tid + THREADS;
            pf0 = *(const float4*)(cb + (size_t)(nk * KT + (i0 >> 1)) * DDIM +
                                   nd * DCHUNK + (i0 & 1) * 4);
            pf1 = *(const float4*)(cb + (size_t)(nk * KT + (i1 >> 1)) * DDIM +
                                   nd * DCHUNK + (i1 & 1) * 4);
        }

        // compute: 4 pixels x 8 codes x 8 d
        const float* zb = z_s + (px_id * 4) * ZS_STRIDE + dc * DCHUNK;
        const float* eb = e_s + cur * KT * ES_STRIDE + c_id * ES_STRIDE;
#pragma unroll
        for (int d4 = 0; d4 < DCHUNK / 4; d4++) {
            float4 zv[4];
#pragma unroll
            for (int i = 0; i < 4; i++)
                zv[i] = *(const float4*)(zb + i * ZS_STRIDE + d4 * 4);
#pragma unroll
            for (int j = 0; j < 8; j++) {
                float4 ev = *(const float4*)(eb + j * 16 * ES_STRIDE + d4 * 4);
#pragma unroll
                for (int i = 0; i < 4; i++) {
                    acc[i][j] = fmaf(zv[i].x, ev.x, acc[i][j]);
                    acc[i][j] = fmaf(zv[i].y, ev.y, acc[i][j]);
                    acc[i][j] = fmaf(zv[i].z, ev.z, acc[i][j]);
                    acc[i][j] = fmaf(zv[i].w, ev.w, acc[i][j]);
                }
            }
        }

        // store prefetched chunk into the other buffer
        if (t + 1 < TCH) {
            int i0 = tid, i1 = tid + THREADS;
            float* dst = e_s + (cur ^ 1) * KT * ES_STRIDE;
            *(float4*)(dst + (i0 >> 1) * ES_STRIDE + (i0 & 1) * 4) = pf0;
            *(float4*)(dst + (i1 >> 1) * ES_STRIDE + (i1 & 1) * 4) = pf1;
        }
        __syncthreads();

        // end of a K-chunk: fold into running argmin, reset accumulators
        if (dc == NDC - 1) {
            const int kc = t >> 5;
#pragma unroll
            for (int j = 0; j < 8; j++) {
                const int code = kc * KT + c_id + 16 * j;
                const float esq = __ldg(&g_esq[code]);
#pragma unroll
                for (int i = 0; i < 4; i++) {
                    // dist = (zsq - 2*cross) + esq; 2x is exact (exponent bump)
                    float d = __fadd_rn(__fadd_rn(zsq_s[px_id * 4 + i],
                                                  -2.0f * acc[i][j]), esq);
                    if (d < best[i]) { best[i] = d; bidx[i] = code; }
                    acc[i][j] = 0.0f;
                }
            }
        }
    }

    // ---- argmin across the 16 code-lanes of each pixel group ----
#pragma unroll
    for (int i = 0; i < 4; i++) {
        float v = best[i];
        int   ix = bidx[i];
#pragma unroll
        for (int off = 8; off >= 1; off >>= 1) {
            float ov = __shfl_xor_sync(0xffffffffu, v, off, 16);
            int   oi = __shfl_xor_sync(0xffffffffu, ix, off, 16);
            if (ov < v || (ov == v && oi < ix)) { v = ov; ix = oi; }
        }
        // Output dtype is float32: indices < 512 are exactly representable.
        if (c_id == 0) out[pix_base + px_id * 4 + i] = (float)ix;
    }
}

extern "C" void kernel_launch(void* const* d_in, const int* in_sizes, int n_in,
                              void* d_out, int out_size) {
    // z_e_x: 16,777,216 elems; codebook: 131,072 elems — identify by size.
    const float* a0 = (const float*)d_in[0];
    const float* a1 = (const float*)d_in[1];
    const float* z  = (in_sizes[0] > in_sizes[1]) ? a0 : a1;
    const float* cb = (in_sizes[0] > in_sizes[1]) ? a1 : a0;
    float* out = (float*)d_out;

    esq_kernel<<<2, 256>>>(cb);
    vq_argmin_kernel<<<NPIX / MT, THREADS>>>(z, cb, out);
}

// round 5
// speedup vs baseline: 1.1786x; 1.1786x over previous
#include <cuda_runtime.h>

#define NPIX 65536      // B*H*W = 64*32*32
#define DDIM 256
#define KCODES 512
#define MT 64           // pixels per CTA
#define KT 128          // codes per K-chunk
#define DCHUNK 8        // d per streamed chunk
#define ZS_STRIDE 260   // 256 + 4 (floats)
#define ES_STRIDE 12    // 8 + 4 pad: 8-lane phases hit banks {0,12,24,4,16,28,8,20}
#define THREADS 128
#define NDC (DDIM / DCHUNK)   // 32 d-chunks
#define NKC (KCODES / KT)     // 4 k-chunks
#define TCH (NKC * NDC)       // 128 total chunks

__device__ float g_esq[KCODES];

// Packed f32x2 FMA (sm_100+): acc = a*b + acc lane-wise on the 2-float pack.
__device__ __forceinline__ void fma2(unsigned long long& acc,
                                     unsigned long long a,
                                     unsigned long long b) {
    asm("fma.rn.f32x2 %0, %1, %2, %0;" : "+l"(acc) : "l"(a), "l"(b));
}

__global__ void esq_kernel(const float* __restrict__ cb) {
    int k = blockIdx.x * blockDim.x + threadIdx.x;
    if (k >= KCODES) return;
    const float4* row = (const float4*)(cb + k * DDIM);
    float sx = 0.f, sy = 0.f, sz = 0.f, sw = 0.f;
#pragma unroll
    for (int i = 0; i < DDIM / 4; i++) {
        float4 v = row[i];
        sx = __fadd_rn(sx, __fmul_rn(v.x, v.x));
        sy = __fadd_rn(sy, __fmul_rn(v.y, v.y));
        sz = __fadd_rn(sz, __fmul_rn(v.z, v.z));
        sw = __fadd_rn(sw, __fmul_rn(v.w, v.w));
    }
    g_esq[k] = __fadd_rn(__fadd_rn(sx, sy), __fadd_rn(sz, sw));
}

__global__ __launch_bounds__(THREADS)
void vq_argmin_kernel(const float* __restrict__ z,
                      const float* __restrict__ cb,
                      float* __restrict__ out) {
    extern __shared__ float smem[];
    float* z_s   = smem;                          // [64][260]  = 66,560 B
    float* e_s   = smem + MT * ZS_STRIDE;         // [2][128][12] = 12,288 B
    float* zsq_s = e_s + 2 * KT * ES_STRIDE;      // [64]

    const int tid   = threadIdx.x;
    const int c_id  = tid & 15;     // 16 code lanes (x8 codes each = 128/k-chunk)
    const int px_id = tid >> 4;     // 8 pixel groups of 8 pixels
    const int pix_base = blockIdx.x * MT;

    // ---- transpose z tile: gmem [b, d, hw] -> z_s[p][d] ----
    {
        const int b   = pix_base >> 10;
        const int hw0 = pix_base & 1023;
        const float* zbase = z + (size_t)b * (DDIM * 1024) + hw0;
#pragma unroll
        for (int it = 0; it < 32; it++) {
            int linear = tid + THREADS * it;      // 0..4095 float4 slots
            int d  = linear >> 4;                 // 0..255
            int p4 = (linear & 15) << 2;          // 0..60
            float4 v = *(const float4*)(zbase + (size_t)d * 1024 + p4);
            z_s[(p4 + 0) * ZS_STRIDE + d] = v.x;
            z_s[(p4 + 1) * ZS_STRIDE + d] = v.y;
            z_s[(p4 + 2) * ZS_STRIDE + d] = v.z;
            z_s[(p4 + 3) * ZS_STRIDE + d] = v.w;
        }
    }
    __syncthreads();

    // ---- per-pixel |z|^2 (square rounded separately, 4-lane pairwise sum) ----
    if (tid < MT) {
        const float4* zr = (const float4*)(z_s + tid * ZS_STRIDE);
        float sx = 0.f, sy = 0.f, sz = 0.f, sw = 0.f;
#pragma unroll
        for (int i = 0; i < DDIM / 4; i++) {
            float4 v = zr[i];
            sx = __fadd_rn(sx, __fmul_rn(v.x, v.x));
            sy = __fadd_rn(sy, __fmul_rn(v.y, v.y));
            sz = __fadd_rn(sz, __fmul_rn(v.z, v.z));
            sw = __fadd_rn(sw, __fmul_rn(v.w, v.w));
        }
        zsq_s[tid] = __fadd_rn(__fadd_rn(sx, sy), __fadd_rn(sz, sw));
    }

    // ---- prefetch chunk 0 (kc=0, dc=0) into buffer 0 ----
    float4 pf0, pf1;
    {
        int i0 = tid, i1 = tid + THREADS;         // 0..255 float4 slots
        pf0 = *(const float4*)(cb + (size_t)(i0 >> 1) * DDIM + (i0 & 1) * 4);
        pf1 = *(const float4*)(cb + (size_t)(i1 >> 1) * DDIM + (i1 & 1) * 4);
        *(float4*)(e_s + (i0 >> 1) * ES_STRIDE + (i0 & 1) * 4) = pf0;
        *(float4*)(e_s + (i1 >> 1) * ES_STRIDE + (i1 & 1) * 4) = pf1;
    }
    __syncthreads();

    float best[8];
    int   bidx[8];
    unsigned long long acc[8][8];   // [pixel][code] even/odd-d packed sums
#pragma unroll
    for (int i = 0; i < 8; i++) {
        best[i] = 3.4e38f; bidx[i] = 0;
#pragma unroll
        for (int j = 0; j < 8; j++) acc[i][j] = 0ULL;
    }

    for (int t = 0; t < TCH; t++) {
        const int cur = t & 1;
        const int dc  = t & (NDC - 1);

        // issue prefetch of chunk t+1 (gmem latency overlaps compute)
        if (t + 1 < TCH) {
            const int nk = (t + 1) >> 5;
            const int nd = (t + 1) & (NDC - 1);
            int i0 = tid, i1 = tid + THREADS;
            pf0 = *(const float4*)(cb + (size_t)(nk * KT + (i0 >> 1)) * DDIM +
                                   nd * DCHUNK + (i0 & 1) * 4);
            pf1 = *(const float4*)(cb + (size_t)(nk * KT + (i1 >> 1)) * DDIM +
                                   nd * DCHUNK + (i1 & 1) * 4);
        }

        // compute: 8 pixels x 8 codes x 8 d (f32x2 packed: 256 FMA2)
        const float* zb = z_s + (px_id * 8) * ZS_STRIDE + dc * DCHUNK;
        const float* eb = e_s + cur * KT * ES_STRIDE + c_id * ES_STRIDE;
#pragma unroll
        for (int d4 = 0; d4 < DCHUNK / 4; d4++) {
            ulonglong2 zv[8];
#pragma unroll
            for (int i = 0; i < 8; i++)
                zv[i] = *(const ulonglong2*)(zb + i * ZS_STRIDE + d4 * 4);
#pragma unroll
            for (int j = 0; j < 8; j++) {
                ulonglong2 ev = *(const ulonglong2*)(eb + j * 16 * ES_STRIDE + d4 * 4);
#pragma unroll
                for (int i = 0; i < 8; i++) fma2(acc[i][j], zv[i].x, ev.x);
#pragma unroll
                for (int i = 0; i < 8; i++) fma2(acc[i][j], zv[i].y, ev.y);
            }
        }

        // store prefetched chunk into the other buffer
        if (t + 1 < TCH) {
            int i0 = tid, i1 = tid + THREADS;
            float* dst = e_s + (cur ^ 1) * KT * ES_STRIDE;
            *(float4*)(dst + (i0 >> 1) * ES_STRIDE + (i0 & 1) * 4) = pf0;
            *(float4*)(dst + (i1 >> 1) * ES_STRIDE + (i1 & 1) * 4) = pf1;
        }
        __syncthreads();

        // end of a K-chunk: fold into running argmin, reset accumulators
        if (dc == NDC - 1) {
            const int kc = t >> 5;
#pragma unroll
            for (int j = 0; j < 8; j++) {
                const int code = kc * KT + c_id + 16 * j;
                const float esq = __ldg(&g_esq[code]);
#pragma unroll
                for (int i = 0; i < 8; i++) {
                    float lo = __uint_as_float((unsigned)(acc[i][j] & 0xffffffffULL));
                    float hi = __uint_as_float((unsigned)(acc[i][j] >> 32));
                    float cross = __fadd_rn(lo, hi);
                    float d = __fadd_rn(__fadd_rn(zsq_s[px_id * 8 + i],
                                                  -2.0f * cross), esq);
                    if (d < best[i]) { best[i] = d; bidx[i] = code; }
                    acc[i][j] = 0ULL;
                }
            }
        }
    }

    // ---- argmin across the 16 code-lanes of each pixel group ----
#pragma unroll
    for (int i = 0; i < 8; i++) {
        float v = best[i];
        int   ix = bidx[i];
#pragma unroll
        for (int off = 8; off >= 1; off >>= 1) {
            float ov = __shfl_xor_sync(0xffffffffu, v, off, 16);
            int   oi = __shfl_xor_sync(0xffffffffu, ix, off, 16);
            if (ov < v || (ov == v && oi < ix)) { v = ov; ix = oi; }
        }
        // Output dtype is float32: indices < 512 exactly representable.
        if (c_id == 0) out[pix_base + px_id * 8 + i] = (float)ix;
    }
}

extern "C" void kernel_launch(void* const* d_in, const int* in_sizes, int n_in,
                              void* d_out, int out_size) {
    // z_e_x: 16,777,216 elems; codebook: 131,072 elems — identify by size.
    const float* a0 = (const float*)d_in[0];
    const float* a1 = (const float*)d_in[1];
    const float* z  = (in_sizes[0] > in_sizes[1]) ? a0 : a1;
    const float* cb = (in_sizes[0] > in_sizes[1]) ? a1 : a0;
    float* out = (float*)d_out;

    const size_t smem_bytes =
        (MT * ZS_STRIDE + 2 * KT * ES_STRIDE + MT) * sizeof(float);
    cudaFuncSetAttribute(vq_argmin_kernel,
                         cudaFuncAttributeMaxDynamicSharedMemorySize,
                         (int)smem_bytes);

    esq_kernel<<<2, 256>>>(cb);
    vq_argmin_kernel<<<NPIX / MT, THREADS, smem_bytes>>>(z, cb, out);
}